// round 14
// baseline (speedup 1.0000x reference)
#include <cuda_runtime.h>
#include <cstdint>

#define N_STRUCT 65536
#define B_BATCH  64
#define L_TEXT   256
#define DIM      256

// ---------------- scratch ----------------
__device__ float g_Q[N_STRUCT * DIM];
__device__ float g_K[B_BATCH * L_TEXT * DIM];
__device__ float g_V[B_BATCH * L_TEXT * DIM];
__device__ float g_Ctx[N_STRUCT * DIM];
__device__ float g_accum[B_BATCH * DIM];
__device__ int   g_offsets[B_BATCH + 1];
__device__ int   g_is64;

// ---------------- helpers ----------------
__device__ __forceinline__ float tf32r(float x) {
    uint32_t u;
    asm("cvt.rna.tf32.f32 %0, %1;" : "=r"(u) : "f"(x));
    return __uint_as_float(u);
}
__device__ __forceinline__ void mma8(float* c, float4 a, float2 b) {
    asm volatile(
        "mma.sync.aligned.m16n8k8.row.col.f32.tf32.tf32.f32 "
        "{%0,%1,%2,%3},{%4,%5,%6,%7},{%8,%9},{%0,%1,%2,%3};"
        : "+f"(c[0]), "+f"(c[1]), "+f"(c[2]), "+f"(c[3])
        : "r"(__float_as_uint(a.x)), "r"(__float_as_uint(a.y)),
          "r"(__float_as_uint(a.z)), "r"(__float_as_uint(a.w)),
          "r"(__float_as_uint(b.x)), "r"(__float_as_uint(b.y)));
}
__device__ __forceinline__ float poly_exp2(float y) {
    float z = y + 12582912.f;
    int nb = __float_as_int(z) << 23;
    float f = y - (z - 12582912.f);
    float p = 1.3333558146e-3f;
    p = fmaf(p, f, 9.6181291076e-3f);
    p = fmaf(p, f, 5.5504108664e-2f);
    p = fmaf(p, f, 2.4022650696e-1f);
    p = fmaf(p, f, 6.9314718056e-1f);
    p = fmaf(p, f, 1.0f);
    return __int_as_float(__float_as_int(p) + nb);
}
#define SCALE_L2E 0.18033688011112042f   // 0.125 * log2(e)

// =====================================================================================
// Setup
// =====================================================================================
__global__ void setup_kernel(const int* __restrict__ sb)
{
    __shared__ int sIs64;
    int tid = threadIdx.x;
    if (tid == 0) {
        sIs64 = (sb[N_STRUCT - 1] == 0) ? 1 : 0;
        g_is64 = sIs64;
    }
    for (int i = tid; i < B_BATCH * DIM; i += blockDim.x) g_accum[i] = 0.f;
    __syncthreads();
    int is64 = sIs64;
    if (tid <= B_BATCH) {
        int lo = 0, hi = N_STRUCT;
        while (lo < hi) {
            int mid = (lo + hi) >> 1;
            int v = is64 ? sb[2 * mid] : sb[mid];
            if (v < tid) lo = mid + 1; else hi = mid;
        }
        g_offsets[tid] = lo;
    }
}

// =====================================================================================
// K1: tf32 GEMM, double-buffered smem. C = A @ W^T + bias.
// Tile 128x128x32; 8 warps 4(M)x2(N). One barrier per k-iter.
// =====================================================================================
#define GB_A0 0
#define GB_W0 4608
#define GB_A1 9216
#define GB_W1 13824
#define GB_FLOATS 18432
#define GB_BYTES (GB_FLOATS * 4)   // 73728

__device__ __forceinline__ void gemm_stage(
    float* sm, int bufA, int bufW,
    const float* __restrict__ A, const float* __restrict__ W,
    int m0, int n0, int k0, int tid)
{
#pragma unroll
    for (int q = 0; q < 4; q++) {
        int f4 = tid + (q << 8);
        int row = f4 >> 3;
        int c4 = (f4 & 7) << 2;
        float4 va = *(const float4*)&A[(size_t)(m0 + row) * 256 + k0 + c4];
        float4 vw = *(const float4*)&W[(size_t)(n0 + row) * 256 + k0 + c4];
        float* da = &sm[bufA + row * 36 + c4];
        float* dw = &sm[bufW + row * 36 + c4];
        da[0] = tf32r(va.x); da[1] = tf32r(va.y); da[2] = tf32r(va.z); da[3] = tf32r(va.w);
        dw[0] = tf32r(vw.x); dw[1] = tf32r(vw.y); dw[2] = tf32r(vw.z); dw[3] = tf32r(vw.w);
    }
}

__global__ __launch_bounds__(256) void gemm_tc(
    const float* __restrict__ A, const float* __restrict__ W,
    const float* __restrict__ bias, float* __restrict__ C)
{
    extern __shared__ float sm[];
    int tid = threadIdx.x;
    int w = tid >> 5, lane = tid & 31;
    int g = lane >> 2, t = lane & 3;
    int wm = w >> 1, wn = w & 1;
    int m0 = blockIdx.x << 7, n0 = blockIdx.y << 7;

    float acc[2][8][4];
#pragma unroll
    for (int mt = 0; mt < 2; mt++)
#pragma unroll
        for (int nt = 0; nt < 8; nt++)
#pragma unroll
            for (int r = 0; r < 4; r++) acc[mt][nt][r] = 0.f;

    gemm_stage(sm, GB_A0, GB_W0, A, W, m0, n0, 0, tid);
    __syncthreads();

    for (int kc = 0; kc < 8; kc++) {
        int bufA = (kc & 1) ? GB_A1 : GB_A0;
        int bufW = (kc & 1) ? GB_W1 : GB_W0;
        if (kc < 7) {
            int nA = (kc & 1) ? GB_A0 : GB_A1;
            int nW = (kc & 1) ? GB_W0 : GB_W1;
            gemm_stage(sm, nA, nW, A, W, m0, n0, (kc + 1) << 5, tid);
        }
#pragma unroll
        for (int ks = 0; ks < 4; ks++) {
            float4 af[2];
#pragma unroll
            for (int mt = 0; mt < 2; mt++) {
                int base = bufA + (wm * 32 + mt * 16 + g) * 36 + ks * 8 + t;
                af[mt].x = sm[base];
                af[mt].y = sm[base + 8 * 36];
                af[mt].z = sm[base + 4];
                af[mt].w = sm[base + 8 * 36 + 4];
            }
#pragma unroll
            for (int nt = 0; nt < 8; nt++) {
                int nb = bufW + (wn * 64 + nt * 8 + g) * 36 + ks * 8 + t;
                float2 bf = make_float2(sm[nb], sm[nb + 4]);
                mma8(acc[0][nt], af[0], bf);
                mma8(acc[1][nt], af[1], bf);
            }
        }
        __syncthreads();
    }
#pragma unroll
    for (int mt = 0; mt < 2; mt++) {
        int row = m0 + wm * 32 + mt * 16 + g;
#pragma unroll
        for (int nt = 0; nt < 8; nt++) {
            int col = n0 + wn * 64 + nt * 8 + t * 2;
            float b0 = __ldg(&bias[col]), b1 = __ldg(&bias[col + 1]);
            float2 o0 = make_float2(acc[mt][nt][0] + b0, acc[mt][nt][1] + b1);
            float2 o1 = make_float2(acc[mt][nt][2] + b0, acc[mt][nt][3] + b1);
            *(float2*)&C[(size_t)row * 256 + col] = o0;
            *(float2*)&C[(size_t)(row + 8) * 256 + col] = o1;
        }
    }
}

// =====================================================================================
// K2a: persistent-KV attention (R9/R11-proven, 247us). Grid = 64 x 4 x 2 = 512 CTAs.
// =====================================================================================
#define SK_OFF   0
#define SV_OFF   18432
#define SQ2_OFF  35840
#define SP2_OFF  40448
#define SRED2_OFF 57344
#define K2A_FLOATS 57600
#define K2A_BYTES (K2A_FLOATS * 4)

__global__ __launch_bounds__(256) void attn_tc()
{
    extern __shared__ float sm[];
    int bx   = blockIdx.x;
    int b    = bx >> 3;
    int h    = (bx >> 1) & 3;
    int slab = bx & 1;
    int off  = g_offsets[b];
    int cnt  = g_offsets[b + 1] - off;
    if (cnt == 0) return;

    int tid = threadIdx.x;
    int w = tid >> 5, lane = tid & 31;
    int g = lane >> 2, t = lane & 3;
    int wm = w >> 2, wn = w & 3;   // 2(M) x 4(N)

    const float4* q4  = (const float4*)(sm + SQ2_OFF);
    const float4* p4  = (const float4*)(sm + SP2_OFF);
    const float2* k2  = (const float2*)(sm + SK_OFF);
    const float2* v2  = (const float2*)(sm + SV_OFF);

    // ---- stage K_h [256 keys x 64 dims] ONCE (scores B-perm) ----
#pragma unroll
    for (int q = 0; q < 16; q++) {
        int f4 = tid + (q << 8);
        int key = f4 >> 4;
        int d4 = (f4 & 15) << 2;
        float4 v = *(const float4*)&g_K[(size_t)((b << 8) + key) * 256 + (h << 6) + d4];
        int ks = d4 >> 3, kth = (d4 >> 2) & 1;
        int kb = (key * 36 + ks * 4) * 2 + kth;
        sm[SK_OFF + kb + 0] = tf32r(v.x); sm[SK_OFF + kb + 2] = tf32r(v.y);
        sm[SK_OFF + kb + 4] = tf32r(v.z); sm[SK_OFF + kb + 6] = tf32r(v.w);
    }
    // ---- stage V_h [256 keys x 64 dims] ONCE (ctx B-perm) ----
#pragma unroll
    for (int q = 0; q < 16; q++) {
        int f4 = tid + (q << 8);
        int key = f4 >> 4;
        int d4 = (f4 & 15) << 2;
        float4 v = *(const float4*)&g_V[(size_t)((b << 8) + key) * 256 + (h << 6) + d4];
        int slotrow = ((key >> 3) << 2) + (key & 3);
        int comp = (key >> 2) & 1;
        int vb = (slotrow * 68 + d4) * 2 + comp;
        sm[SV_OFF + vb + 0] = tf32r(v.x); sm[SV_OFF + vb + 2] = tf32r(v.y);
        sm[SV_OFF + vb + 4] = tf32r(v.z); sm[SV_OFF + vb + 6] = tf32r(v.w);
    }
    __syncthreads();

    int nch = (cnt + 63) >> 6;
    for (int c = slab; c < nch; c += 2) {
        int s0 = off + (c << 6);
        int rows = min(64, cnt - (c << 6));

        // ---- stage Q chunk [64x64] (A-perm), zero pad ----
#pragma unroll
        for (int q = 0; q < 4; q++) {
            int f4 = tid + (q << 8);
            int row = f4 >> 4;
            int d4 = (f4 & 15) << 2;
            float4 v = make_float4(0.f, 0.f, 0.f, 0.f);
            if (row < rows)
                v = *(const float4*)&g_Q[(size_t)(s0 + row) * 256 + (h << 6) + d4];
            int blk = row >> 4, gg = row & 7, half = (row >> 3) & 1;
            int ks = d4 >> 3, kth = (d4 >> 2) & 1;
            int ab = (blk * 288 + gg * 36 + ks * 4) * 4 + half + 2 * kth;
            sm[SQ2_OFF + ab + 0] = tf32r(v.x); sm[SQ2_OFF + ab + 4] = tf32r(v.y);
            sm[SQ2_OFF + ab + 8] = tf32r(v.z); sm[SQ2_OFF + ab + 12] = tf32r(v.w);
        }
        __syncthreads();   // (a)

        // ---- scores S[64x256] = Q @ K^T ----
        float sc[2][8][4];
#pragma unroll
        for (int mt = 0; mt < 2; mt++)
#pragma unroll
            for (int nt = 0; nt < 8; nt++)
#pragma unroll
                for (int r = 0; r < 4; r++) sc[mt][nt][r] = 0.f;
#pragma unroll
        for (int ks = 0; ks < 8; ks++) {
            float4 af[2];
#pragma unroll
            for (int mt = 0; mt < 2; mt++)
                af[mt] = q4[(wm * 2 + mt) * 288 + g * 36 + ks * 4 + t];
#pragma unroll
            for (int nt = 0; nt < 8; nt++) {
                float2 bf = k2[(wn * 64 + nt * 8 + g) * 36 + ks * 4 + t];
                mma8(sc[0][nt], af[0], bf);
                mma8(sc[1][nt], af[1], bf);
            }
        }

        // ---- exp (no max pass; FMA pipe) + row partial sums ----
        float psum[4];
#pragma unroll
        for (int rid = 0; rid < 4; rid++) {
            int mt = rid >> 1, h2 = rid & 1;
            float s = 0.f;
#pragma unroll
            for (int nt = 0; nt < 8; nt++) {
#pragma unroll
                for (int j = 0; j < 2; j++) {
                    float y = sc[mt][nt][h2 * 2 + j] * SCALE_L2E;
                    float e = poly_exp2(y);
                    sc[mt][nt][h2 * 2 + j] = e;
                    s += e;
                }
            }
            s += __shfl_xor_sync(0xffffffffu, s, 1);
            s += __shfl_xor_sync(0xffffffffu, s, 2);
            psum[rid] = s;
        }
        if (t == 0) {
#pragma unroll
            for (int rid = 0; rid < 4; rid++) {
                int r = wm * 32 + (rid >> 1) * 16 + g + (rid & 1) * 8;
                sm[SRED2_OFF + wn * 64 + r] = psum[rid];
            }
        }
        // ---- store unnormalized P in A-perm layout ----
#pragma unroll
        for (int mt = 0; mt < 2; mt++) {
            int blkb = (wm * 2 + mt) * 1056 + g * 132;
#pragma unroll
            for (int nt = 0; nt < 8; nt++) {
                int slot = blkb + (wn * 8 + nt) * 4;
#pragma unroll
                for (int cix = 0; cix < 4; cix++) {
                    int addr = (slot + 2 * (t & 1) + (cix & 1)) * 4 + (cix >> 1) + 2 * (t >> 1);
                    sm[SP2_OFF + addr] = tf32r(sc[mt][nt][cix]);
                }
            }
        }
        __syncthreads();   // (b)

        float inv[4];
#pragma unroll
        for (int rid = 0; rid < 4; rid++) {
            int r = wm * 32 + (rid >> 1) * 16 + g + (rid & 1) * 8;
            float tot = sm[SRED2_OFF + r] + sm[SRED2_OFF + 64 + r] +
                        sm[SRED2_OFF + 128 + r] + sm[SRED2_OFF + 192 + r];
            inv[rid] = 1.f / tot;
        }

        // ---- ctx C[64x64] = P @ V ----
        float cc[2][2][4];
#pragma unroll
        for (int mt = 0; mt < 2; mt++)
#pragma unroll
            for (int nt = 0; nt < 2; nt++)
#pragma unroll
                for (int r = 0; r < 4; r++) cc[mt][nt][r] = 0.f;
#pragma unroll 8
        for (int ks = 0; ks < 32; ks++) {
            float4 af[2];
#pragma unroll
            for (int mt = 0; mt < 2; mt++)
                af[mt] = p4[(wm * 2 + mt) * 1056 + g * 132 + ks * 4 + t];
#pragma unroll
            for (int nt = 0; nt < 2; nt++) {
                float2 bf = v2[(ks * 4 + t) * 68 + wn * 16 + nt * 8 + g];
                mma8(cc[0][nt], af[0], bf);
                mma8(cc[1][nt], af[1], bf);
            }
        }
        // ---- epilogue: normalize, write ctx ----
#pragma unroll
        for (int mt = 0; mt < 2; mt++)
#pragma unroll
            for (int h2 = 0; h2 < 2; h2++) {
                int r = wm * 32 + mt * 16 + g + h2 * 8;
                if (r < rows) {
                    float iv = inv[mt * 2 + h2];
#pragma unroll
                    for (int nt = 0; nt < 2; nt++) {
                        int col = (h << 6) + wn * 16 + nt * 8 + t * 2;
                        float2 o = make_float2(cc[mt][nt][h2 * 2] * iv,
                                               cc[mt][nt][h2 * 2 + 1] * iv);
                        *(float2*)&g_Ctx[(size_t)(s0 + r) * 256 + col] = o;
                    }
                }
            }
        __syncthreads();   // (d)
    }
}

// =====================================================================================
// K2b: out_proj + LN + per-batch accumulation (R11-proven).
// =====================================================================================
#define OB_A   0
#define OB_W   4608
#define OB_RM  13824
#define OB_RS  14336
#define OB_CB  14848
#define OB_RB  15872
#define K2B_FLOATS 16000
#define K2B_BYTES (K2B_FLOATS * 4)

__global__ __launch_bounds__(512) void outln_tc(
    const float* __restrict__ Wo, const float* __restrict__ bo,
    const float* __restrict__ lnw, const float* __restrict__ lnb,
    const int* __restrict__ sb)
{
    extern __shared__ float sm[];
    int* rowB = (int*)&sm[OB_RB];
    int tid = threadIdx.x;
    int w = tid >> 5, lane = tid & 31;
    int g = lane >> 2, t = lane & 3;
    int wm = w >> 2, wn = w & 3;
    int m0 = blockIdx.x << 7;

    if (tid < 128) {
        int idx = m0 + tid;
        rowB[tid] = g_is64 ? sb[2 * idx] : sb[idx];
    }

    float acc[2][8][4];
#pragma unroll
    for (int mt = 0; mt < 2; mt++)
#pragma unroll
        for (int nt = 0; nt < 8; nt++)
#pragma unroll
            for (int r = 0; r < 4; r++) acc[mt][nt][r] = 0.f;

    for (int kc = 0; kc < 8; kc++) {
        int k0 = kc << 5;
#pragma unroll
        for (int q = 0; q < 2; q++) {
            int f4 = tid + (q << 9);
            int row = f4 >> 3;
            int c4 = (f4 & 7) << 2;
            float4 v = *(const float4*)&g_Ctx[(size_t)(m0 + row) * 256 + k0 + c4];
            float* d = &sm[OB_A + row * 36 + c4];
            d[0] = tf32r(v.x); d[1] = tf32r(v.y); d[2] = tf32r(v.z); d[3] = tf32r(v.w);
        }
#pragma unroll
        for (int q = 0; q < 4; q++) {
            int f4 = tid + (q << 9);
            int row = f4 >> 3;
            int c4 = (f4 & 7) << 2;
            float4 v = *(const float4*)&Wo[(size_t)row * 256 + k0 + c4];
            float* d = &sm[OB_W + row * 36 + c4];
            d[0] = tf32r(v.x); d[1] = tf32r(v.y); d[2] = tf32r(v.z); d[3] = tf32r(v.w);
        }
        __syncthreads();
#pragma unroll
        for (int ks = 0; ks < 4; ks++) {
            float4 af[2];
#pragma unroll
            for (int mt = 0; mt < 2; mt++) {
                int base = OB_A + (wm * 32 + mt * 16 + g) * 36 + ks * 8 + t;
                af[mt].x = sm[base];
                af[mt].y = sm[base + 8 * 36];
                af[mt].z = sm[base + 4];
                af[mt].w = sm[base + 8 * 36 + 4];
            }
#pragma unroll
            for (int nt = 0; nt < 8; nt++) {
                int nb = OB_W + (wn * 64 + nt * 8 + g) * 36 + ks * 8 + t;
                float2 bf = make_float2(sm[nb], sm[nb + 4]);
                mma8(acc[0][nt], af[0], bf);
                mma8(acc[1][nt], af[1], bf);
            }
        }
        __syncthreads();
    }

#pragma unroll
    for (int nt = 0; nt < 8; nt++) {
        int col = wn * 64 + nt * 8 + t * 2;
        float b0 = __ldg(&bo[col]), b1 = __ldg(&bo[col + 1]);
#pragma unroll
        for (int mt = 0; mt < 2; mt++) {
            acc[mt][nt][0] += b0; acc[mt][nt][1] += b1;
            acc[mt][nt][2] += b0; acc[mt][nt][3] += b1;
        }
    }

    float s4[4], q4r[4];
#pragma unroll
    for (int rid = 0; rid < 4; rid++) {
        int mt = rid >> 1, h2 = rid & 1;
        float s = 0.f, qq = 0.f;
#pragma unroll
        for (int nt = 0; nt < 8; nt++)
#pragma unroll
            for (int j = 0; j < 2; j++) {
                float v = acc[mt][nt][h2 * 2 + j];
                s += v; qq += v * v;
            }
        s  += __shfl_xor_sync(0xffffffffu, s, 1);
        s  += __shfl_xor_sync(0xffffffffu, s, 2);
        qq += __shfl_xor_sync(0xffffffffu, qq, 1);
        qq += __shfl_xor_sync(0xffffffffu, qq, 2);
        s4[rid] = s; q4r[rid] = qq;
    }
    if (t == 0) {
#pragma unroll
        for (int rid = 0; rid < 4; rid++) {
            int r = wm * 32 + (rid >> 1) * 16 + g + (rid & 1) * 8;
            sm[OB_RM + wn * 128 + r] = s4[rid];
            sm[OB_RS + wn * 128 + r] = q4r[rid];
        }
    }
    __syncthreads();
    float mu[4], inv[4];
#pragma unroll
    for (int rid = 0; rid < 4; rid++) {
        int r = wm * 32 + (rid >> 1) * 16 + g + (rid & 1) * 8;
        float S  = sm[OB_RM + r] + sm[OB_RM + 128 + r] + sm[OB_RM + 256 + r] + sm[OB_RM + 384 + r];
        float SQ = sm[OB_RS + r] + sm[OB_RS + 128 + r] + sm[OB_RS + 256 + r] + sm[OB_RS + 384 + r];
        float m = S * (1.f / 256.f);
        float var = SQ * (1.f / 256.f) - m * m;
        mu[rid] = m;
        inv[rid] = rsqrtf(var + 1e-5f);
    }

    int b0r = rowB[0], bLr = rowB[127];
    bool uniform = (b0r == bLr);

    if (uniform) {
#pragma unroll
        for (int rid = 0; rid < 4; rid++) {
            int mt = rid >> 1, h2 = rid & 1;
#pragma unroll
            for (int nt = 0; nt < 8; nt++) {
                int col = wn * 64 + nt * 8 + t * 2;
                acc[mt][nt][h2 * 2]     = (acc[mt][nt][h2 * 2]     - mu[rid]) * inv[rid] * __ldg(&lnw[col])     + __ldg(&lnb[col]);
                acc[mt][nt][h2 * 2 + 1] = (acc[mt][nt][h2 * 2 + 1] - mu[rid]) * inv[rid] * __ldg(&lnw[col + 1]) + __ldg(&lnb[col + 1]);
            }
        }
#pragma unroll
        for (int nt = 0; nt < 8; nt++) {
            float cs0 = acc[0][nt][0] + acc[0][nt][2] + acc[1][nt][0] + acc[1][nt][2];
            float cs1 = acc[0][nt][1] + acc[0][nt][3] + acc[1][nt][1] + acc[1][nt][3];
            cs0 += __shfl_xor_sync(0xffffffffu, cs0, 4);
            cs0 += __shfl_xor_sync(0xffffffffu, cs0, 8);
            cs0 += __shfl_xor_sync(0xffffffffu, cs0, 16);
            cs1 += __shfl_xor_sync(0xffffffffu, cs1, 4);
            cs1 += __shfl_xor_sync(0xffffffffu, cs1, 8);
            cs1 += __shfl_xor_sync(0xffffffffu, cs1, 16);
            if (g == 0) {
                int col = wn * 64 + nt * 8 + t * 2;
                sm[OB_CB + wm * 256 + col]     = cs0;
                sm[OB_CB + wm * 256 + col + 1] = cs1;
            }
        }
        __syncthreads();
        if (tid < 256) {
            float tot = sm[OB_CB + tid] + sm[OB_CB + 256 + tid] +
                        sm[OB_CB + 512 + tid] + sm[OB_CB + 768 + tid];
            atomicAdd(&g_accum[(b0r << 8) + tid], tot);
        }
    } else {
#pragma unroll
        for (int rid = 0; rid < 4; rid++) {
            int mt = rid >> 1, h2 = rid & 1;
            int r = wm * 32 + mt * 16 + g + h2 * 8;
            int bb = rowB[r];
#pragma unroll
            for (int nt = 0; nt < 8; nt++) {
                int col = wn * 64 + nt * 8 + t * 2;
                float y0 = (acc[mt][nt][h2 * 2]     - mu[rid]) * inv[rid] * __ldg(&lnw[col])     + __ldg(&lnb[col]);
                float y1 = (acc[mt][nt][h2 * 2 + 1] - mu[rid]) * inv[rid] * __ldg(&lnw[col + 1]) + __ldg(&lnb[col + 1]);
                atomicAdd(&g_accum[(bb << 8) + col],     y0);
                atomicAdd(&g_accum[(bb << 8) + col + 1], y1);
            }
        }
    }
}

// =====================================================================================
// Finalize
// =====================================================================================
__global__ __launch_bounds__(256) void finalize_kernel(
    const float* __restrict__ fcw, const float* __restrict__ fcb,
    float* __restrict__ out)
{
    int b = blockIdx.x;
    int tid = threadIdx.x;
    __shared__ float s[256];
    s[tid] = g_accum[(b << 8) + tid];
    __syncthreads();
    int cnt = g_offsets[b + 1] - g_offsets[b];
    if (cnt == 0) { out[(b << 8) + tid] = 0.f; return; }
    float acc = 0.f;
    const float* wrow = fcw + (size_t)tid * 256;
#pragma unroll 8
    for (int k = 0; k < 256; k++) acc += s[k] * __ldg(&wrow[k]);
    out[(b << 8) + tid] = acc / (float)cnt + __ldg(&fcb[tid]);
}

// =====================================================================================
// Launch
// =====================================================================================
extern "C" void kernel_launch(void* const* d_in, const int* in_sizes, int n_in,
                              void* d_out, int out_size)
{
    const float* structf = (const float*)d_in[0];
    const float* textf   = (const float*)d_in[1];
    const int*   sb      = (const int*)d_in[2];
    const float* inW     = (const float*)d_in[3];
    const float* inB     = (const float*)d_in[4];
    const float* outW    = (const float*)d_in[5];
    const float* outB    = (const float*)d_in[6];
    const float* lnw     = (const float*)d_in[7];
    const float* lnb     = (const float*)d_in[8];
    const float* fcw     = (const float*)d_in[9];
    const float* fcb     = (const float*)d_in[10];
    float* out = (float*)d_out;

    float *pQ, *pK, *pV;
    cudaGetSymbolAddress((void**)&pQ, g_Q);
    cudaGetSymbolAddress((void**)&pK, g_K);
    cudaGetSymbolAddress((void**)&pV, g_V);

    cudaFuncSetAttribute(gemm_tc, cudaFuncAttributeMaxDynamicSharedMemorySize, GB_BYTES);
    cudaFuncSetAttribute(attn_tc, cudaFuncAttributeMaxDynamicSharedMemorySize, K2A_BYTES);
    cudaFuncSetAttribute(outln_tc, cudaFuncAttributeMaxDynamicSharedMemorySize, K2B_BYTES);

    setup_kernel<<<1, 256>>>(sb);

    gemm_tc<<<dim3((B_BATCH * L_TEXT) / 128, 2), 256, GB_BYTES>>>(textf, inW + DIM * DIM,     inB + DIM,     pK);
    gemm_tc<<<dim3((B_BATCH * L_TEXT) / 128, 2), 256, GB_BYTES>>>(textf, inW + 2 * DIM * DIM, inB + 2 * DIM, pV);
    gemm_tc<<<dim3(N_STRUCT / 128, 2), 256, GB_BYTES>>>(structf, inW, inB, pQ);

    attn_tc<<<B_BATCH * 4 * 2, 256, K2A_BYTES>>>();
    outln_tc<<<N_STRUCT / 128, 512, K2B_BYTES>>>(outW, outB, lnw, lnb, sb);
    finalize_kernel<<<B_BATCH, 256>>>(fcw, fcb, out);
}

// round 16
// speedup vs baseline: 1.1000x; 1.1000x over previous
#include <cuda_runtime.h>
#include <cstdint>

#define N_STRUCT 65536
#define B_BATCH  64
#define L_TEXT   256
#define DIM      256
#define SLABS    3

// ---------------- scratch ----------------
__device__ float g_Q[N_STRUCT * DIM];
__device__ float g_K[B_BATCH * L_TEXT * DIM];
__device__ float g_V[B_BATCH * L_TEXT * DIM];
__device__ float g_Ctx[N_STRUCT * DIM];
__device__ float g_accum[B_BATCH * DIM];
__device__ int   g_offsets[B_BATCH + 1];
__device__ int   g_is64;

// ---------------- helpers ----------------
__device__ __forceinline__ float tf32r(float x) {
    uint32_t u;
    asm("cvt.rna.tf32.f32 %0, %1;" : "=r"(u) : "f"(x));
    return __uint_as_float(u);
}
__device__ __forceinline__ void mma8(float* c, float4 a, float2 b) {
    asm volatile(
        "mma.sync.aligned.m16n8k8.row.col.f32.tf32.tf32.f32 "
        "{%0,%1,%2,%3},{%4,%5,%6,%7},{%8,%9},{%0,%1,%2,%3};"
        : "+f"(c[0]), "+f"(c[1]), "+f"(c[2]), "+f"(c[3])
        : "r"(__float_as_uint(a.x)), "r"(__float_as_uint(a.y)),
          "r"(__float_as_uint(a.z)), "r"(__float_as_uint(a.w)),
          "r"(__float_as_uint(b.x)), "r"(__float_as_uint(b.y)));
}
__device__ __forceinline__ float poly_exp2(float y) {
    float z = y + 12582912.f;
    int nb = __float_as_int(z) << 23;
    float f = y - (z - 12582912.f);
    float p = 1.3333558146e-3f;
    p = fmaf(p, f, 9.6181291076e-3f);
    p = fmaf(p, f, 5.5504108664e-2f);
    p = fmaf(p, f, 2.4022650696e-1f);
    p = fmaf(p, f, 6.9314718056e-1f);
    p = fmaf(p, f, 1.0f);
    return __int_as_float(__float_as_int(p) + nb);
}
#define SCALE_L2E 0.18033688011112042f   // 0.125 * log2(e)

// =====================================================================================
// Setup
// =====================================================================================
__global__ void setup_kernel(const int* __restrict__ sb)
{
    __shared__ int sIs64;
    int tid = threadIdx.x;
    if (tid == 0) {
        sIs64 = (sb[N_STRUCT - 1] == 0) ? 1 : 0;
        g_is64 = sIs64;
    }
    for (int i = tid; i < B_BATCH * DIM; i += blockDim.x) g_accum[i] = 0.f;
    __syncthreads();
    int is64 = sIs64;
    if (tid <= B_BATCH) {
        int lo = 0, hi = N_STRUCT;
        while (lo < hi) {
            int mid = (lo + hi) >> 1;
            int v = is64 ? sb[2 * mid] : sb[mid];
            if (v < tid) lo = mid + 1; else hi = mid;
        }
        g_offsets[tid] = lo;
    }
}

// =====================================================================================
// K1: tf32 GEMM (R9-proven). C = A @ W^T + bias.
// =====================================================================================
__global__ __launch_bounds__(256) void gemm_tc(
    const float* __restrict__ A, const float* __restrict__ W,
    const float* __restrict__ bias, float* __restrict__ C)
{
    __shared__ float sA[128 * 36];
    __shared__ float sW[128 * 36];
    int tid = threadIdx.x;
    int w = tid >> 5, lane = tid & 31;
    int g = lane >> 2, t = lane & 3;
    int wm = w >> 1, wn = w & 1;
    int m0 = blockIdx.x << 7, n0 = blockIdx.y << 7;

    float acc[2][8][4];
#pragma unroll
    for (int mt = 0; mt < 2; mt++)
#pragma unroll
        for (int nt = 0; nt < 8; nt++)
#pragma unroll
            for (int r = 0; r < 4; r++) acc[mt][nt][r] = 0.f;

    for (int k0 = 0; k0 < 256; k0 += 32) {
#pragma unroll
        for (int q = 0; q < 4; q++) {
            int f4 = tid + (q << 8);
            int row = f4 >> 3;
            int c4 = (f4 & 7) << 2;
            float4 va = *(const float4*)&A[(size_t)(m0 + row) * 256 + k0 + c4];
            float4 vw = *(const float4*)&W[(size_t)(n0 + row) * 256 + k0 + c4];
            float* da = &sA[row * 36 + c4];
            float* dw = &sW[row * 36 + c4];
            da[0] = tf32r(va.x); da[1] = tf32r(va.y); da[2] = tf32r(va.z); da[3] = tf32r(va.w);
            dw[0] = tf32r(vw.x); dw[1] = tf32r(vw.y); dw[2] = tf32r(vw.z); dw[3] = tf32r(vw.w);
        }
        __syncthreads();
#pragma unroll
        for (int ks = 0; ks < 4; ks++) {
            float4 af[2];
#pragma unroll
            for (int mt = 0; mt < 2; mt++) {
                int base = (wm * 32 + mt * 16 + g) * 36 + ks * 8 + t;
                af[mt].x = sA[base];
                af[mt].y = sA[base + 8 * 36];
                af[mt].z = sA[base + 4];
                af[mt].w = sA[base + 8 * 36 + 4];
            }
#pragma unroll
            for (int nt = 0; nt < 8; nt++) {
                int nb = (wn * 64 + nt * 8 + g) * 36 + ks * 8 + t;
                float2 bf = make_float2(sW[nb], sW[nb + 4]);
                mma8(acc[0][nt], af[0], bf);
                mma8(acc[1][nt], af[1], bf);
            }
        }
        __syncthreads();
    }
#pragma unroll
    for (int mt = 0; mt < 2; mt++) {
        int row = m0 + wm * 32 + mt * 16 + g;
#pragma unroll
        for (int nt = 0; nt < 8; nt++) {
            int col = n0 + wn * 64 + nt * 8 + t * 2;
            float b0 = __ldg(&bias[col]), b1 = __ldg(&bias[col + 1]);
            float2 o0 = make_float2(acc[mt][nt][0] + b0, acc[mt][nt][1] + b1);
            float2 o1 = make_float2(acc[mt][nt][2] + b0, acc[mt][nt][3] + b1);
            *(float2*)&C[(size_t)row * 256 + col] = o0;
            *(float2*)&C[(size_t)(row + 8) * 256 + col] = o1;
        }
    }
}

// =====================================================================================
// K2a: persistent-KV attention (R9/R11-proven body). Grid = 64 x 4 x SLABS CTAs.
// =====================================================================================
#define SK_OFF   0
#define SV_OFF   18432
#define SQ2_OFF  35840
#define SP2_OFF  40448
#define SRED2_OFF 57344
#define K2A_FLOATS 57600
#define K2A_BYTES (K2A_FLOATS * 4)

__global__ __launch_bounds__(256) void attn_tc()
{
    extern __shared__ float sm[];
    int bx   = blockIdx.x;
    int b    = bx / (4 * SLABS);
    int rem  = bx - b * (4 * SLABS);
    int h    = rem / SLABS;
    int slab = rem - h * SLABS;
    int off  = g_offsets[b];
    int cnt  = g_offsets[b + 1] - off;
    if (cnt == 0) return;

    int tid = threadIdx.x;
    int w = tid >> 5, lane = tid & 31;
    int g = lane >> 2, t = lane & 3;
    int wm = w >> 2, wn = w & 3;   // 2(M) x 4(N)

    const float4* q4  = (const float4*)(sm + SQ2_OFF);
    const float4* p4  = (const float4*)(sm + SP2_OFF);
    const float2* k2  = (const float2*)(sm + SK_OFF);
    const float2* v2  = (const float2*)(sm + SV_OFF);

    // ---- stage K_h [256 keys x 64 dims] ONCE (scores B-perm) ----
#pragma unroll
    for (int q = 0; q < 16; q++) {
        int f4 = tid + (q << 8);
        int key = f4 >> 4;
        int d4 = (f4 & 15) << 2;
        float4 v = *(const float4*)&g_K[(size_t)((b << 8) + key) * 256 + (h << 6) + d4];
        int ks = d4 >> 3, kth = (d4 >> 2) & 1;
        int kb = (key * 36 + ks * 4) * 2 + kth;
        sm[SK_OFF + kb + 0] = tf32r(v.x); sm[SK_OFF + kb + 2] = tf32r(v.y);
        sm[SK_OFF + kb + 4] = tf32r(v.z); sm[SK_OFF + kb + 6] = tf32r(v.w);
    }
    // ---- stage V_h [256 keys x 64 dims] ONCE (ctx B-perm) ----
#pragma unroll
    for (int q = 0; q < 16; q++) {
        int f4 = tid + (q << 8);
        int key = f4 >> 4;
        int d4 = (f4 & 15) << 2;
        float4 v = *(const float4*)&g_V[(size_t)((b << 8) + key) * 256 + (h << 6) + d4];
        int slotrow = ((key >> 3) << 2) + (key & 3);
        int comp = (key >> 2) & 1;
        int vb = (slotrow * 68 + d4) * 2 + comp;
        sm[SV_OFF + vb + 0] = tf32r(v.x); sm[SV_OFF + vb + 2] = tf32r(v.y);
        sm[SV_OFF + vb + 4] = tf32r(v.z); sm[SV_OFF + vb + 6] = tf32r(v.w);
    }
    __syncthreads();

    int nch = (cnt + 63) >> 6;
    for (int c = slab; c < nch; c += SLABS) {
        int s0 = off + (c << 6);
        int rows = min(64, cnt - (c << 6));

        // ---- stage Q chunk [64x64] (A-perm), zero pad ----
#pragma unroll
        for (int q = 0; q < 4; q++) {
            int f4 = tid + (q << 8);
            int row = f4 >> 4;
            int d4 = (f4 & 15) << 2;
            float4 v = make_float4(0.f, 0.f, 0.f, 0.f);
            if (row < rows)
                v = *(const float4*)&g_Q[(size_t)(s0 + row) * 256 + (h << 6) + d4];
            int blk = row >> 4, gg = row & 7, half = (row >> 3) & 1;
            int ks = d4 >> 3, kth = (d4 >> 2) & 1;
            int ab = (blk * 288 + gg * 36 + ks * 4) * 4 + half + 2 * kth;
            sm[SQ2_OFF + ab + 0] = tf32r(v.x); sm[SQ2_OFF + ab + 4] = tf32r(v.y);
            sm[SQ2_OFF + ab + 8] = tf32r(v.z); sm[SQ2_OFF + ab + 12] = tf32r(v.w);
        }
        __syncthreads();   // (a)

        // ---- scores S[64x256] = Q @ K^T ----
        float sc[2][8][4];
#pragma unroll
        for (int mt = 0; mt < 2; mt++)
#pragma unroll
            for (int nt = 0; nt < 8; nt++)
#pragma unroll
                for (int r = 0; r < 4; r++) sc[mt][nt][r] = 0.f;
#pragma unroll
        for (int ks = 0; ks < 8; ks++) {
            float4 af[2];
#pragma unroll
            for (int mt = 0; mt < 2; mt++)
                af[mt] = q4[(wm * 2 + mt) * 288 + g * 36 + ks * 4 + t];
#pragma unroll
            for (int nt = 0; nt < 8; nt++) {
                float2 bf = k2[(wn * 64 + nt * 8 + g) * 36 + ks * 4 + t];
                mma8(sc[0][nt], af[0], bf);
                mma8(sc[1][nt], af[1], bf);
            }
        }

        // ---- exp (no max pass; FMA pipe) + row partial sums ----
        float psum[4];
#pragma unroll
        for (int rid = 0; rid < 4; rid++) {
            int mt = rid >> 1, h2 = rid & 1;
            float s = 0.f;
#pragma unroll
            for (int nt = 0; nt < 8; nt++) {
#pragma unroll
                for (int j = 0; j < 2; j++) {
                    float y = sc[mt][nt][h2 * 2 + j] * SCALE_L2E;
                    float e = poly_exp2(y);
                    sc[mt][nt][h2 * 2 + j] = e;
                    s += e;
                }
            }
            s += __shfl_xor_sync(0xffffffffu, s, 1);
            s += __shfl_xor_sync(0xffffffffu, s, 2);
            psum[rid] = s;
        }
        if (t == 0) {
#pragma unroll
            for (int rid = 0; rid < 4; rid++) {
                int r = wm * 32 + (rid >> 1) * 16 + g + (rid & 1) * 8;
                sm[SRED2_OFF + wn * 64 + r] = psum[rid];
            }
        }
        // ---- store unnormalized P in A-perm layout ----
#pragma unroll
        for (int mt = 0; mt < 2; mt++) {
            int blkb = (wm * 2 + mt) * 1056 + g * 132;
#pragma unroll
            for (int nt = 0; nt < 8; nt++) {
                int slot = blkb + (wn * 8 + nt) * 4;
#pragma unroll
                for (int cix = 0; cix < 4; cix++) {
                    int addr = (slot + 2 * (t & 1) + (cix & 1)) * 4 + (cix >> 1) + 2 * (t >> 1);
                    sm[SP2_OFF + addr] = tf32r(sc[mt][nt][cix]);
                }
            }
        }
        __syncthreads();   // (b)

        float inv[4];
#pragma unroll
        for (int rid = 0; rid < 4; rid++) {
            int r = wm * 32 + (rid >> 1) * 16 + g + (rid & 1) * 8;
            float tot = sm[SRED2_OFF + r] + sm[SRED2_OFF + 64 + r] +
                        sm[SRED2_OFF + 128 + r] + sm[SRED2_OFF + 192 + r];
            inv[rid] = 1.f / tot;
        }

        // ---- ctx C[64x64] = P @ V ----
        float cc[2][2][4];
#pragma unroll
        for (int mt = 0; mt < 2; mt++)
#pragma unroll
            for (int nt = 0; nt < 2; nt++)
#pragma unroll
                for (int r = 0; r < 4; r++) cc[mt][nt][r] = 0.f;
#pragma unroll 8
        for (int ks = 0; ks < 32; ks++) {
            float4 af[2];
#pragma unroll
            for (int mt = 0; mt < 2; mt++)
                af[mt] = p4[(wm * 2 + mt) * 1056 + g * 132 + ks * 4 + t];
#pragma unroll
            for (int nt = 0; nt < 2; nt++) {
                float2 bf = v2[(ks * 4 + t) * 68 + wn * 16 + nt * 8 + g];
                mma8(cc[0][nt], af[0], bf);
                mma8(cc[1][nt], af[1], bf);
            }
        }
        // ---- epilogue: normalize, write ctx ----
#pragma unroll
        for (int mt = 0; mt < 2; mt++)
#pragma unroll
            for (int h2 = 0; h2 < 2; h2++) {
                int r = wm * 32 + mt * 16 + g + h2 * 8;
                if (r < rows) {
                    float iv = inv[mt * 2 + h2];
#pragma unroll
                    for (int nt = 0; nt < 2; nt++) {
                        int col = (h << 6) + wn * 16 + nt * 8 + t * 2;
                        float2 o = make_float2(cc[mt][nt][h2 * 2] * iv,
                                               cc[mt][nt][h2 * 2 + 1] * iv);
                        *(float2*)&g_Ctx[(size_t)(s0 + r) * 256 + col] = o;
                    }
                }
            }
        __syncthreads();   // (d)
    }
}

// =====================================================================================
// K2b: out_proj + LN + per-batch accumulation (R11-proven).
// =====================================================================================
#define OB_A   0
#define OB_W   4608
#define OB_RM  13824
#define OB_RS  14336
#define OB_CB  14848
#define OB_RB  15872
#define K2B_FLOATS 16000
#define K2B_BYTES (K2B_FLOATS * 4)

__global__ __launch_bounds__(512) void outln_tc(
    const float* __restrict__ Wo, const float* __restrict__ bo,
    const float* __restrict__ lnw, const float* __restrict__ lnb,
    const int* __restrict__ sb)
{
    extern __shared__ float sm[];
    int* rowB = (int*)&sm[OB_RB];
    int tid = threadIdx.x;
    int w = tid >> 5, lane = tid & 31;
    int g = lane >> 2, t = lane & 3;
    int wm = w >> 2, wn = w & 3;
    int m0 = blockIdx.x << 7;

    if (tid < 128) {
        int idx = m0 + tid;
        rowB[tid] = g_is64 ? sb[2 * idx] : sb[idx];
    }

    float acc[2][8][4];
#pragma unroll
    for (int mt = 0; mt < 2; mt++)
#pragma unroll
        for (int nt = 0; nt < 8; nt++)
#pragma unroll
            for (int r = 0; r < 4; r++) acc[mt][nt][r] = 0.f;

    for (int kc = 0; kc < 8; kc++) {
        int k0 = kc << 5;
#pragma unroll
        for (int q = 0; q < 2; q++) {
            int f4 = tid + (q << 9);
            int row = f4 >> 3;
            int c4 = (f4 & 7) << 2;
            float4 v = *(const float4*)&g_Ctx[(size_t)(m0 + row) * 256 + k0 + c4];
            float* d = &sm[OB_A + row * 36 + c4];
            d[0] = tf32r(v.x); d[1] = tf32r(v.y); d[2] = tf32r(v.z); d[3] = tf32r(v.w);
        }
#pragma unroll
        for (int q = 0; q < 4; q++) {
            int f4 = tid + (q << 9);
            int row = f4 >> 3;
            int c4 = (f4 & 7) << 2;
            float4 v = *(const float4*)&Wo[(size_t)row * 256 + k0 + c4];
            float* d = &sm[OB_W + row * 36 + c4];
            d[0] = tf32r(v.x); d[1] = tf32r(v.y); d[2] = tf32r(v.z); d[3] = tf32r(v.w);
        }
        __syncthreads();
#pragma unroll
        for (int ks = 0; ks < 4; ks++) {
            float4 af[2];
#pragma unroll
            for (int mt = 0; mt < 2; mt++) {
                int base = OB_A + (wm * 32 + mt * 16 + g) * 36 + ks * 8 + t;
                af[mt].x = sm[base];
                af[mt].y = sm[base + 8 * 36];
                af[mt].z = sm[base + 4];
                af[mt].w = sm[base + 8 * 36 + 4];
            }
#pragma unroll
            for (int nt = 0; nt < 8; nt++) {
                int nb = OB_W + (wn * 64 + nt * 8 + g) * 36 + ks * 8 + t;
                float2 bf = make_float2(sm[nb], sm[nb + 4]);
                mma8(acc[0][nt], af[0], bf);
                mma8(acc[1][nt], af[1], bf);
            }
        }
        __syncthreads();
    }

#pragma unroll
    for (int nt = 0; nt < 8; nt++) {
        int col = wn * 64 + nt * 8 + t * 2;
        float b0 = __ldg(&bo[col]), b1 = __ldg(&bo[col + 1]);
#pragma unroll
        for (int mt = 0; mt < 2; mt++) {
            acc[mt][nt][0] += b0; acc[mt][nt][1] += b1;
            acc[mt][nt][2] += b0; acc[mt][nt][3] += b1;
        }
    }

    float s4[4], q4r[4];
#pragma unroll
    for (int rid = 0; rid < 4; rid++) {
        int mt = rid >> 1, h2 = rid & 1;
        float s = 0.f, qq = 0.f;
#pragma unroll
        for (int nt = 0; nt < 8; nt++)
#pragma unroll
            for (int j = 0; j < 2; j++) {
                float v = acc[mt][nt][h2 * 2 + j];
                s += v; qq += v * v;
            }
        s  += __shfl_xor_sync(0xffffffffu, s, 1);
        s  += __shfl_xor_sync(0xffffffffu, s, 2);
        qq += __shfl_xor_sync(0xffffffffu, qq, 1);
        qq += __shfl_xor_sync(0xffffffffu, qq, 2);
        s4[rid] = s; q4r[rid] = qq;
    }
    if (t == 0) {
#pragma unroll
        for (int rid = 0; rid < 4; rid++) {
            int r = wm * 32 + (rid >> 1) * 16 + g + (rid & 1) * 8;
            sm[OB_RM + wn * 128 + r] = s4[rid];
            sm[OB_RS + wn * 128 + r] = q4r[rid];
        }
    }
    __syncthreads();
    float mu[4], inv[4];
#pragma unroll
    for (int rid = 0; rid < 4; rid++) {
        int r = wm * 32 + (rid >> 1) * 16 + g + (rid & 1) * 8;
        float S  = sm[OB_RM + r] + sm[OB_RM + 128 + r] + sm[OB_RM + 256 + r] + sm[OB_RM + 384 + r];
        float SQ = sm[OB_RS + r] + sm[OB_RS + 128 + r] + sm[OB_RS + 256 + r] + sm[OB_RS + 384 + r];
        float m = S * (1.f / 256.f);
        float var = SQ * (1.f / 256.f) - m * m;
        mu[rid] = m;
        inv[rid] = rsqrtf(var + 1e-5f);
    }

    int b0r = rowB[0], bLr = rowB[127];
    bool uniform = (b0r == bLr);

    if (uniform) {
#pragma unroll
        for (int rid = 0; rid < 4; rid++) {
            int mt = rid >> 1, h2 = rid & 1;
#pragma unroll
            for (int nt = 0; nt < 8; nt++) {
                int col = wn * 64 + nt * 8 + t * 2;
                acc[mt][nt][h2 * 2]     = (acc[mt][nt][h2 * 2]     - mu[rid]) * inv[rid] * __ldg(&lnw[col])     + __ldg(&lnb[col]);
                acc[mt][nt][h2 * 2 + 1] = (acc[mt][nt][h2 * 2 + 1] - mu[rid]) * inv[rid] * __ldg(&lnw[col + 1]) + __ldg(&lnb[col + 1]);
            }
        }
#pragma unroll
        for (int nt = 0; nt < 8; nt++) {
            float cs0 = acc[0][nt][0] + acc[0][nt][2] + acc[1][nt][0] + acc[1][nt][2];
            float cs1 = acc[0][nt][1] + acc[0][nt][3] + acc[1][nt][1] + acc[1][nt][3];
            cs0 += __shfl_xor_sync(0xffffffffu, cs0, 4);
            cs0 += __shfl_xor_sync(0xffffffffu, cs0, 8);
            cs0 += __shfl_xor_sync(0xffffffffu, cs0, 16);
            cs1 += __shfl_xor_sync(0xffffffffu, cs1, 4);
            cs1 += __shfl_xor_sync(0xffffffffu, cs1, 8);
            cs1 += __shfl_xor_sync(0xffffffffu, cs1, 16);
            if (g == 0) {
                int col = wn * 64 + nt * 8 + t * 2;
                sm[OB_CB + wm * 256 + col]     = cs0;
                sm[OB_CB + wm * 256 + col + 1] = cs1;
            }
        }
        __syncthreads();
        if (tid < 256) {
            float tot = sm[OB_CB + tid] + sm[OB_CB + 256 + tid] +
                        sm[OB_CB + 512 + tid] + sm[OB_CB + 768 + tid];
            atomicAdd(&g_accum[(b0r << 8) + tid], tot);
        }
    } else {
#pragma unroll
        for (int rid = 0; rid < 4; rid++) {
            int mt = rid >> 1, h2 = rid & 1;
            int r = wm * 32 + mt * 16 + g + h2 * 8;
            int bb = rowB[r];
#pragma unroll
            for (int nt = 0; nt < 8; nt++) {
                int col = wn * 64 + nt * 8 + t * 2;
                float y0 = (acc[mt][nt][h2 * 2]     - mu[rid]) * inv[rid] * __ldg(&lnw[col])     + __ldg(&lnb[col]);
                float y1 = (acc[mt][nt][h2 * 2 + 1] - mu[rid]) * inv[rid] * __ldg(&lnw[col + 1]) + __ldg(&lnb[col + 1]);
                atomicAdd(&g_accum[(bb << 8) + col],     y0);
                atomicAdd(&g_accum[(bb << 8) + col + 1], y1);
            }
        }
    }
}

// =====================================================================================
// Finalize
// =====================================================================================
__global__ __launch_bounds__(256) void finalize_kernel(
    const float* __restrict__ fcw, const float* __restrict__ fcb,
    float* __restrict__ out)
{
    int b = blockIdx.x;
    int tid = threadIdx.x;
    __shared__ float s[256];
    s[tid] = g_accum[(b << 8) + tid];
    __syncthreads();
    int cnt = g_offsets[b + 1] - g_offsets[b];
    if (cnt == 0) { out[(b << 8) + tid] = 0.f; return; }
    float acc = 0.f;
    const float* wrow = fcw + (size_t)tid * 256;
#pragma unroll 8
    for (int k = 0; k < 256; k++) acc += s[k] * __ldg(&wrow[k]);
    out[(b << 8) + tid] = acc / (float)cnt + __ldg(&fcb[tid]);
}

// =====================================================================================
// Launch
// =====================================================================================
extern "C" void kernel_launch(void* const* d_in, const int* in_sizes, int n_in,
                              void* d_out, int out_size)
{
    const float* structf = (const float*)d_in[0];
    const float* textf   = (const float*)d_in[1];
    const int*   sb      = (const int*)d_in[2];
    const float* inW     = (const float*)d_in[3];
    const float* inB     = (const float*)d_in[4];
    const float* outW    = (const float*)d_in[5];
    const float* outB    = (const float*)d_in[6];
    const float* lnw     = (const float*)d_in[7];
    const float* lnb     = (const float*)d_in[8];
    const float* fcw     = (const float*)d_in[9];
    const float* fcb     = (const float*)d_in[10];
    float* out = (float*)d_out;

    float *pQ, *pK, *pV;
    cudaGetSymbolAddress((void**)&pQ, g_Q);
    cudaGetSymbolAddress((void**)&pK, g_K);
    cudaGetSymbolAddress((void**)&pV, g_V);

    cudaFuncSetAttribute(attn_tc, cudaFuncAttributeMaxDynamicSharedMemorySize, K2A_BYTES);
    cudaFuncSetAttribute(outln_tc, cudaFuncAttributeMaxDynamicSharedMemorySize, K2B_BYTES);

    setup_kernel<<<1, 256>>>(sb);

    gemm_tc<<<dim3((B_BATCH * L_TEXT) / 128, 2), 256>>>(textf, inW + DIM * DIM,     inB + DIM,     pK);
    gemm_tc<<<dim3((B_BATCH * L_TEXT) / 128, 2), 256>>>(textf, inW + 2 * DIM * DIM, inB + 2 * DIM, pV);
    gemm_tc<<<dim3(N_STRUCT / 128, 2), 256>>>(structf, inW, inB, pQ);

    attn_tc<<<B_BATCH * 4 * SLABS, 256, K2A_BYTES>>>();
    outln_tc<<<N_STRUCT / 128, 512, K2B_BYTES>>>(outW, outB, lnw, lnb, sb);
    finalize_kernel<<<B_BATCH, 256>>>(fcw, fcb, out);
}